// round 3
// baseline (speedup 1.0000x reference)
#include <cuda_runtime.h>

// WaveGNN: B=16, N=2048, D=128, L=3
//   per layer: hw = h @ W ; agg = adj^T @ hw ; h = relu(LN(agg + b + h))

#define BATCH 16
#define NN    2048
#define DD    128
#define BK    16

typedef unsigned long long u64;

__device__ __forceinline__ u64 pk2(float x, float y) {
    u64 r; asm("mov.b64 %0,{%1,%2};" : "=l"(r) : "f"(x), "f"(y)); return r;
}
__device__ __forceinline__ void upk2(float& x, float& y, u64 v) {
    asm("mov.b64 {%0,%1},%2;" : "=f"(x), "=f"(y) : "l"(v));
}
__device__ __forceinline__ void ffma2(u64& c, u64 a, u64 b) {
    asm("fma.rn.f32x2 %0,%1,%2,%0;" : "+l"(c) : "l"(a), "l"(b));
}

// Scratch (allocation-free): hw buffer + two ping-pong h buffers (16 MB each).
__device__ float g_hw[BATCH * NN * DD];
__device__ float g_h0[BATCH * NN * DD];
__device__ float g_h1[BATCH * NN * DD];

// 16-k-step micro-kernel on a 128x128 tile; 8x8 per-thread tile, f32x2 packed.
template <int ASTRIDE>
__device__ __forceinline__ void mma_tile(const float* As, const float* Bs,
                                         u64 (*acc)[4], int tx, int ty) {
#pragma unroll
    for (int k = 0; k < BK; k++) {
        const float* ar = As + k * ASTRIDE + ty * 8;
        const float* br = Bs + k * 128 + tx * 8;
        float4 a0 = *(const float4*)ar;
        float4 a1 = *(const float4*)(ar + 4);
        float4 b0 = *(const float4*)br;
        float4 b1 = *(const float4*)(br + 4);
        float av[8] = {a0.x, a0.y, a0.z, a0.w, a1.x, a1.y, a1.z, a1.w};
        u64 bb[4] = {pk2(b0.x, b0.y), pk2(b0.z, b0.w),
                     pk2(b1.x, b1.y), pk2(b1.z, b1.w)};
#pragma unroll
        for (int mm = 0; mm < 8; mm++) {
            u64 ap = pk2(av[mm], av[mm]);
#pragma unroll
            for (int nq = 0; nq < 4; nq++) ffma2(acc[mm][nq], ap, bb[nq]);
        }
    }
}

// ---------------------------------------------------------------------------
// linear_kernel: hw[m,n] = sum_k h[m,k] * W[k,n];  m in [0, BATCH*NN)
// grid: 256 blocks x 256 threads
// ---------------------------------------------------------------------------
__global__ void __launch_bounds__(256, 2)
linear_kernel(const float* __restrict__ X, int src, const float* __restrict__ W) {
    const float* h = (src == 0) ? X : (src == 1 ? g_h0 : g_h1);

    __shared__ float As[2][BK][132];  // padded: transpose-on-store
    __shared__ float Bs[2][BK][128];

    int tid = threadIdx.x;
    int tx = tid & 15, ty = tid >> 4;
    int m0 = blockIdx.x * 128;

    u64 acc[8][4];
#pragma unroll
    for (int i = 0; i < 8; i++)
#pragma unroll
        for (int j = 0; j < 4; j++) acc[i][j] = 0ull;

    float4 pa[2], pb[2];

    // prefetch tile 0
#pragma unroll
    for (int p = 0; p < 2; p++) {
        int idx4 = tid + p * 256;
        int am = idx4 >> 2, akg = (idx4 & 3) * 4;
        pa[p] = *(const float4*)(h + (size_t)(m0 + am) * DD + akg);
        int bk = (tid >> 5) + p * 8, bn = (tid & 31) * 4;
        pb[p] = *(const float4*)(W + (size_t)bk * DD + bn);
    }
#pragma unroll
    for (int p = 0; p < 2; p++) {
        int idx4 = tid + p * 256;
        int am = idx4 >> 2, akg = (idx4 & 3) * 4;
        As[0][akg + 0][am] = pa[p].x;
        As[0][akg + 1][am] = pa[p].y;
        As[0][akg + 2][am] = pa[p].z;
        As[0][akg + 3][am] = pa[p].w;
        int bk = (tid >> 5) + p * 8, bn = (tid & 31) * 4;
        *(float4*)&Bs[0][bk][bn] = pb[p];
    }
    __syncthreads();

    const int NK = DD / BK;  // 8
    for (int kt = 0; kt < NK; kt++) {
        int cur = kt & 1;
        if (kt + 1 < NK) {
            int k0 = (kt + 1) * BK;
#pragma unroll
            for (int p = 0; p < 2; p++) {
                int idx4 = tid + p * 256;
                int am = idx4 >> 2, akg = (idx4 & 3) * 4;
                pa[p] = *(const float4*)(h + (size_t)(m0 + am) * DD + k0 + akg);
                int bk = (tid >> 5) + p * 8, bn = (tid & 31) * 4;
                pb[p] = *(const float4*)(W + (size_t)(k0 + bk) * DD + bn);
            }
        }
        mma_tile<132>(&As[cur][0][0], &Bs[cur][0][0], acc, tx, ty);
        if (kt + 1 < NK) {
            int nxt = cur ^ 1;
#pragma unroll
            for (int p = 0; p < 2; p++) {
                int idx4 = tid + p * 256;
                int am = idx4 >> 2, akg = (idx4 & 3) * 4;
                As[nxt][akg + 0][am] = pa[p].x;
                As[nxt][akg + 1][am] = pa[p].y;
                As[nxt][akg + 2][am] = pa[p].z;
                As[nxt][akg + 3][am] = pa[p].w;
                int bk = (tid >> 5) + p * 8, bn = (tid & 31) * 4;
                *(float4*)&Bs[nxt][bk][bn] = pb[p];
            }
            __syncthreads();
        }
    }

    float* outp = g_hw + (size_t)(m0 + ty * 8) * DD + tx * 8;
#pragma unroll
    for (int mm = 0; mm < 8; mm++) {
        float4 o0, o1;
        upk2(o0.x, o0.y, acc[mm][0]);
        upk2(o0.z, o0.w, acc[mm][1]);
        upk2(o1.x, o1.y, acc[mm][2]);
        upk2(o1.z, o1.w, acc[mm][3]);
        *(float4*)(outp + (size_t)mm * DD) = o0;
        *(float4*)(outp + (size_t)mm * DD + 4) = o1;
    }
}

// ---------------------------------------------------------------------------
// gcn_kernel: for batch b, row-tile j0:
//   agg[j, e] = sum_i adj[b,i,j] * hw[b,i,e]          (adj^T GEMM, K = 2048)
//   z = agg + bias[e] + hin[b,j,e]
//   out = relu( (z - mu) * rsqrt(var + eps) * gamma + beta )   (LN over e)
// grid: (NN/128, BATCH) x 256 threads
// ---------------------------------------------------------------------------
__global__ void __launch_bounds__(256, 2)
gcn_kernel(const float* __restrict__ adj, const float* __restrict__ X, int src,
           int dst, float* __restrict__ dout, const float* __restrict__ bias,
           const float* __restrict__ gamma, const float* __restrict__ beta) {
    const float* hin = (src == 0) ? X : (src == 1 ? g_h0 : g_h1);
    float* hout = (dst == 2) ? dout : (dst == 0 ? g_h0 : g_h1);

    __shared__ float As[2][BK][128];
    __shared__ float Bs[2][BK][128];

    int tid = threadIdx.x;
    int tx = tid & 15, ty = tid >> 4;
    int b = blockIdx.y;
    int j0 = blockIdx.x * 128;

    const float* adj_b = adj + (size_t)b * NN * NN;
    const float* hw_b = g_hw + (size_t)b * NN * DD;

    u64 acc[8][4];
#pragma unroll
    for (int i = 0; i < 8; i++)
#pragma unroll
        for (int j = 0; j < 4; j++) acc[i][j] = 0ull;

    int lk = tid >> 5;          // 0..7
    int lm = (tid & 31) * 4;    // 0..124

    float4 pa[2], pb[2];
#pragma unroll
    for (int p = 0; p < 2; p++) {
        int k = lk + p * 8;
        pa[p] = *(const float4*)(adj_b + (size_t)k * NN + j0 + lm);
        pb[p] = *(const float4*)(hw_b + (size_t)k * DD + lm);
    }
#pragma unroll
    for (int p = 0; p < 2; p++) {
        int k = lk + p * 8;
        *(float4*)&As[0][k][lm] = pa[p];
        *(float4*)&Bs[0][k][lm] = pb[p];
    }
    __syncthreads();

    const int NK = NN / BK;  // 128
    for (int kt = 0; kt < NK; kt++) {
        int cur = kt & 1;
        if (kt + 1 < NK) {
            int k0 = (kt + 1) * BK;
#pragma unroll
            for (int p = 0; p < 2; p++) {
                int k = k0 + lk + p * 8;
                pa[p] = *(const float4*)(adj_b + (size_t)k * NN + j0 + lm);
                pb[p] = *(const float4*)(hw_b + (size_t)k * DD + lm);
            }
        }
        mma_tile<128>(&As[cur][0][0], &Bs[cur][0][0], acc, tx, ty);
        if (kt + 1 < NK) {
            int nxt = cur ^ 1;
#pragma unroll
            for (int p = 0; p < 2; p++) {
                int k = lk + p * 8;
                *(float4*)&As[nxt][k][lm] = pa[p];
                *(float4*)&Bs[nxt][k][lm] = pb[p];
            }
            __syncthreads();
        }
    }

    // ---------------- fused epilogue: bias + residual + LayerNorm + ReLU ----
    __syncthreads();                 // everyone done reading smem tiles
    float* red = &As[0][0][0];       // reuse 16 KB: [0,2048)=sum, [2048,4096)=sumsq

    float4 g0 = *(const float4*)(gamma + tx * 8);
    float4 g1 = *(const float4*)(gamma + tx * 8 + 4);
    float4 e0 = *(const float4*)(beta + tx * 8);
    float4 e1 = *(const float4*)(beta + tx * 8 + 4);
    float4 bi0 = *(const float4*)(bias + tx * 8);
    float4 bi1 = *(const float4*)(bias + tx * 8 + 4);

    const float* resp = hin + (size_t)b * NN * DD + (size_t)(j0 + ty * 8) * DD + tx * 8;
    float zv[8][8];

#pragma unroll
    for (int mm = 0; mm < 8; mm++) {
        float4 r0 = *(const float4*)(resp + (size_t)mm * DD);
        float4 r1 = *(const float4*)(resp + (size_t)mm * DD + 4);
        float z[8];
        upk2(z[0], z[1], acc[mm][0]);
        upk2(z[2], z[3], acc[mm][1]);
        upk2(z[4], z[5], acc[mm][2]);
        upk2(z[6], z[7], acc[mm][3]);
        z[0] += bi0.x + r0.x; z[1] += bi0.y + r0.y;
        z[2] += bi0.z + r0.z; z[3] += bi0.w + r0.w;
        z[4] += bi1.x + r1.x; z[5] += bi1.y + r1.y;
        z[6] += bi1.z + r1.z; z[7] += bi1.w + r1.w;
        float s = 0.f, q = 0.f;
#pragma unroll
        for (int n = 0; n < 8; n++) {
            s += z[n];
            q += z[n] * z[n];
            zv[mm][n] = z[n];
        }
        red[(ty * 8 + mm) * 16 + tx] = s;
        red[2048 + (ty * 8 + mm) * 16 + tx] = q;
    }
    __syncthreads();

    float gg[8] = {g0.x, g0.y, g0.z, g0.w, g1.x, g1.y, g1.z, g1.w};
    float ee[8] = {e0.x, e0.y, e0.z, e0.w, e1.x, e1.y, e1.z, e1.w};
    float* outp = hout + (size_t)b * NN * DD + (size_t)(j0 + ty * 8) * DD + tx * 8;

#pragma unroll
    for (int mm = 0; mm < 8; mm++) {
        float s = 0.f, q = 0.f;
#pragma unroll
        for (int t = 0; t < 16; t++) {
            s += red[(ty * 8 + mm) * 16 + t];
            q += red[2048 + (ty * 8 + mm) * 16 + t];
        }
        float mu = s * (1.0f / DD);
        float var = q * (1.0f / DD) - mu * mu;
        float rstd = rsqrtf(var + 1e-5f);
        float4 o0, o1;
        float y[8];
#pragma unroll
        for (int n = 0; n < 8; n++)
            y[n] = fmaxf(0.f, (zv[mm][n] - mu) * rstd * gg[n] + ee[n]);
        o0.x = y[0]; o0.y = y[1]; o0.z = y[2]; o0.w = y[3];
        o1.x = y[4]; o1.y = y[5]; o1.z = y[6]; o1.w = y[7];
        *(float4*)(outp + (size_t)mm * DD) = o0;
        *(float4*)(outp + (size_t)mm * DD + 4) = o1;
    }
}

// ---------------------------------------------------------------------------
extern "C" void kernel_launch(void* const* d_in, const int* in_sizes, int n_in,
                              void* d_out, int out_size) {
    (void)in_sizes; (void)n_in; (void)out_size;
    const float* X      = (const float*)d_in[0];
    const float* adj    = (const float*)d_in[1];
    const float* Ws     = (const float*)d_in[2];
    const float* bs     = (const float*)d_in[3];
    const float* gammas = (const float*)d_in[4];
    const float* betas  = (const float*)d_in[5];
    float* out = (float*)d_out;

    dim3 ggrid(NN / 128, BATCH);
    // layer l: src selector (0=X, 1=g_h0, 2=g_h1), dst selector (0=g_h0, 1=g_h1, 2=d_out)
    for (int l = 0; l < 3; l++) {
        int src = (l == 0) ? 0 : l;            // 0, 1, 2
        int dst = (l == 2) ? 2 : l;            // 0, 1, 2
        linear_kernel<<<(BATCH * NN) / 128, 256>>>(X, src, Ws + (size_t)l * DD * DD);
        gcn_kernel<<<ggrid, 256>>>(adj, X, src, dst, out,
                                   bs + (size_t)l * DD,
                                   gammas + (size_t)l * DD,
                                   betas + (size_t)l * DD);
    }
}

// round 5
// speedup vs baseline: 2.4299x; 2.4299x over previous
#include <cuda_runtime.h>
#include <cstdint>

// WaveGNN: B=16, N=2048, D=128, L=3
//   per layer: hw = h @ W ; agg = adj^T @ hw ; h = relu(LN(agg + b + h))
// agg GEMM on tensor cores via generic-target mma.sync tf32 (m16n8k8),
// operands staged with cp.async; fragment gather does the adj transpose.

#define BATCH 16
#define NN    2048
#define DD    128
#define BK    16

// gcn tiling
#define CTJ   256          // j rows per CTA
#define KC    32           // K (i) rows per pipeline chunk
#define NKC   (NN / KC)    // 64 chunks
#define ASTR  260          // padded smem stride for adj tile  (260 % 32 == 4)
#define BSTR  132          // padded smem stride for hw  tile  (132 % 32 == 4)
#define STG_F (KC * ASTR + KC * BSTR)      // floats per stage = 12544
#define NSTG  3
#define DYN_SMEM (NSTG * STG_F * 4)        // 150528 bytes

typedef unsigned long long u64;

// ---------------- scratch (static device globals; no runtime alloc) --------
__device__ float g_hw[BATCH * NN * DD];
__device__ float g_h0[BATCH * NN * DD];
__device__ float g_h1[BATCH * NN * DD];

// ---------------- helpers ---------------------------------------------------
__device__ __forceinline__ uint32_t smem_u32(const void* p) {
    uint32_t a;
    asm("{ .reg .u64 t; cvta.to.shared.u64 t, %1; cvt.u32.u64 %0, t; }"
        : "=r"(a) : "l"(p));
    return a;
}

__device__ __forceinline__ void cpa16(uint32_t dst, const void* src) {
    asm volatile("cp.async.cg.shared.global [%0], [%1], 16;"
                 :: "r"(dst), "l"(src) : "memory");
}
#define CPA_COMMIT() asm volatile("cp.async.commit_group;" ::: "memory")
#define CPA_WAIT1()  asm volatile("cp.async.wait_group 1;" ::: "memory")
#define CPA_WAIT0()  asm volatile("cp.async.wait_group 0;" ::: "memory")

__device__ __forceinline__ void mma_tf32(float* d, const uint32_t* a,
                                         const uint32_t* b) {
    asm volatile(
        "mma.sync.aligned.m16n8k8.row.col.f32.tf32.tf32.f32 "
        "{%0,%1,%2,%3}, {%4,%5,%6,%7}, {%8,%9}, {%0,%1,%2,%3};"
        : "+f"(d[0]), "+f"(d[1]), "+f"(d[2]), "+f"(d[3])
        : "r"(a[0]), "r"(a[1]), "r"(a[2]), "r"(a[3]), "r"(b[0]), "r"(b[1]));
}

__device__ __forceinline__ float tf32_rna(float v) {
    uint32_t u;
    asm("cvt.rna.tf32.f32 %0, %1;" : "=r"(u) : "f"(v));
    return __uint_as_float(u);
}

// f32x2 helpers for the SIMT linear kernel
__device__ __forceinline__ u64 pk2(float x, float y) {
    u64 r; asm("mov.b64 %0,{%1,%2};" : "=l"(r) : "f"(x), "f"(y)); return r;
}
__device__ __forceinline__ void upk2(float& x, float& y, u64 v) {
    asm("mov.b64 {%0,%1},%2;" : "=f"(x), "=f"(y) : "l"(v));
}
__device__ __forceinline__ void ffma2(u64& c, u64 a, u64 b) {
    asm("fma.rn.f32x2 %0,%1,%2,%0;" : "+l"(c) : "l"(a), "l"(b));
}

// ---------------------------------------------------------------------------
// linear_kernel: hw[m,n] = sum_k h[m,k] * W[k,n]; output pre-rounded to tf32
// ---------------------------------------------------------------------------
__device__ __forceinline__ void mma_tile_s(const float* As, const float* Bs,
                                           u64 (*acc)[4], int tx, int ty) {
#pragma unroll
    for (int k = 0; k < BK; k++) {
        const float* ar = As + k * 132 + ty * 8;
        const float* br = Bs + k * 128 + tx * 8;
        float4 a0 = *(const float4*)ar;
        float4 a1 = *(const float4*)(ar + 4);
        float4 b0 = *(const float4*)br;
        float4 b1 = *(const float4*)(br + 4);
        float av[8] = {a0.x, a0.y, a0.z, a0.w, a1.x, a1.y, a1.z, a1.w};
        u64 bb[4] = {pk2(b0.x, b0.y), pk2(b0.z, b0.w),
                     pk2(b1.x, b1.y), pk2(b1.z, b1.w)};
#pragma unroll
        for (int mm = 0; mm < 8; mm++) {
            u64 ap = pk2(av[mm], av[mm]);
#pragma unroll
            for (int nq = 0; nq < 4; nq++) ffma2(acc[mm][nq], ap, bb[nq]);
        }
    }
}

__global__ void __launch_bounds__(256, 2)
linear_kernel(const float* __restrict__ h, const float* __restrict__ W,
              float* __restrict__ out) {
    __shared__ float As[2][BK][132];
    __shared__ float Bs[2][BK][128];

    int tid = threadIdx.x;
    int tx = tid & 15, ty = tid >> 4;
    int m0 = blockIdx.x * 128;

    u64 acc[8][4];
#pragma unroll
    for (int i = 0; i < 8; i++)
#pragma unroll
        for (int j = 0; j < 4; j++) acc[i][j] = 0ull;

    float4 pa[2], pb[2];
#pragma unroll
    for (int p = 0; p < 2; p++) {
        int idx4 = tid + p * 256;
        int am = idx4 >> 2, akg = (idx4 & 3) * 4;
        pa[p] = *(const float4*)(h + (size_t)(m0 + am) * DD + akg);
        int bk = (tid >> 5) + p * 8, bn = (tid & 31) * 4;
        pb[p] = *(const float4*)(W + (size_t)bk * DD + bn);
    }
#pragma unroll
    for (int p = 0; p < 2; p++) {
        int idx4 = tid + p * 256;
        int am = idx4 >> 2, akg = (idx4 & 3) * 4;
        As[0][akg + 0][am] = pa[p].x;
        As[0][akg + 1][am] = pa[p].y;
        As[0][akg + 2][am] = pa[p].z;
        As[0][akg + 3][am] = pa[p].w;
        int bk = (tid >> 5) + p * 8, bn = (tid & 31) * 4;
        *(float4*)&Bs[0][bk][bn] = pb[p];
    }
    __syncthreads();

    const int NK = DD / BK;
    for (int kt = 0; kt < NK; kt++) {
        int cur = kt & 1;
        if (kt + 1 < NK) {
            int k0 = (kt + 1) * BK;
#pragma unroll
            for (int p = 0; p < 2; p++) {
                int idx4 = tid + p * 256;
                int am = idx4 >> 2, akg = (idx4 & 3) * 4;
                pa[p] = *(const float4*)(h + (size_t)(m0 + am) * DD + k0 + akg);
                int bk = (tid >> 5) + p * 8, bn = (tid & 31) * 4;
                pb[p] = *(const float4*)(W + (size_t)(k0 + bk) * DD + bn);
            }
        }
        mma_tile_s(&As[cur][0][0], &Bs[cur][0][0], acc, tx, ty);
        if (kt + 1 < NK) {
            int nxt = cur ^ 1;
#pragma unroll
            for (int p = 0; p < 2; p++) {
                int idx4 = tid + p * 256;
                int am = idx4 >> 2, akg = (idx4 & 3) * 4;
                As[nxt][akg + 0][am] = pa[p].x;
                As[nxt][akg + 1][am] = pa[p].y;
                As[nxt][akg + 2][am] = pa[p].z;
                As[nxt][akg + 3][am] = pa[p].w;
                int bk = (tid >> 5) + p * 8, bn = (tid & 31) * 4;
                *(float4*)&Bs[nxt][bk][bn] = pb[p];
            }
            __syncthreads();
        }
    }

    float* outp = out + (size_t)(m0 + ty * 8) * DD + tx * 8;
#pragma unroll
    for (int mm = 0; mm < 8; mm++) {
        float o[8];
        upk2(o[0], o[1], acc[mm][0]);
        upk2(o[2], o[3], acc[mm][1]);
        upk2(o[4], o[5], acc[mm][2]);
        upk2(o[6], o[7], acc[mm][3]);
        float4 v0, v1;
        v0.x = tf32_rna(o[0]); v0.y = tf32_rna(o[1]);
        v0.z = tf32_rna(o[2]); v0.w = tf32_rna(o[3]);
        v1.x = tf32_rna(o[4]); v1.y = tf32_rna(o[5]);
        v1.z = tf32_rna(o[6]); v1.w = tf32_rna(o[7]);
        *(float4*)(outp + (size_t)mm * DD) = v0;
        *(float4*)(outp + (size_t)mm * DD + 4) = v1;
    }
}

// ---------------------------------------------------------------------------
// gcn_kernel (tf32 mma.sync):
//   D[j,e] = sum_i adj[b,i,j] * hw[b,i,e]  (A gathered transposed from smem)
//   out = relu(LN(D + bias + hin))
// grid (NN/CTJ=8, BATCH) x 256 threads (8 warps, warp tile 64x64)
// ---------------------------------------------------------------------------
__global__ void __launch_bounds__(256, 1)
gcn_kernel(const float* __restrict__ adj, const float* __restrict__ hw,
           const float* __restrict__ hin, float* __restrict__ hout,
           const float* __restrict__ bias, const float* __restrict__ gamma,
           const float* __restrict__ beta) {
    extern __shared__ float smem[];
    __shared__ float red_s[CTJ][2][2];
    __shared__ float bias_s[DD], gamma_s[DD], beta_s[DD];

    const int tid = threadIdx.x;
    const int lane = tid & 31;
    const int wid = tid >> 5;
    const int warp_m = wid & 3;      // 4 m-warps x 64 rows
    const int warp_n = wid >> 2;     // 2 n-warps x 64 cols
    const int qm = lane >> 2;        // 0..7
    const int qn = lane & 3;         // 0..3
    const int b = blockIdx.y;
    const int j0 = blockIdx.x * CTJ;

    if (tid < DD) {
        bias_s[tid] = bias[tid];
        gamma_s[tid] = gamma[tid];
        beta_s[tid] = beta[tid];
    }

    const float* adj_b = adj + (size_t)b * NN * NN;
    const float* hw_b = hw + (size_t)b * NN * DD;
    const uint32_t smem_b = smem_u32(smem);

    float d[4][8][4];
#pragma unroll
    for (int mt = 0; mt < 4; mt++)
#pragma unroll
        for (int nt = 0; nt < 8; nt++)
#pragma unroll
            for (int c = 0; c < 4; c++) d[mt][nt][c] = 0.f;

    // ---- chunk loader (cp.async) -----------------------------------------
    auto load_chunk = [&](int kt, int s) {
        uint32_t a_base = smem_b + (uint32_t)(s * STG_F) * 4;
        uint32_t b_base = a_base + (uint32_t)(KC * ASTR) * 4;
        const float* asrc = adj_b + (size_t)(kt * KC) * NN + j0;
        const float* bsrc = hw_b + (size_t)(kt * KC) * DD;
#pragma unroll
        for (int p = 0; p < 8; p++) {             // adj tile: 32 x 256
            int v = tid + p * 256;
            int r = v >> 6, c4 = (v & 63) * 4;
            cpa16(a_base + (uint32_t)(r * ASTR + c4) * 4,
                  asrc + (size_t)r * NN + c4);
        }
#pragma unroll
        for (int p = 0; p < 4; p++) {             // hw tile: 32 x 128
            int v = tid + p * 256;
            int r = v >> 5, c4 = (v & 31) * 4;
            cpa16(b_base + (uint32_t)(r * BSTR + c4) * 4,
                  bsrc + (size_t)r * DD + c4);
        }
        CPA_COMMIT();
    };

    load_chunk(0, 0);
    load_chunk(1, 1);

    for (int kt = 0; kt < NKC; kt++) {
        CPA_WAIT1();
        __syncthreads();
        if (kt + 2 < NKC) load_chunk(kt + 2, (kt + 2) % NSTG);

        const float* As = smem + (size_t)(kt % NSTG) * STG_F;
        const float* Bs = As + KC * ASTR;
        const uint32_t* Asu = (const uint32_t*)As;
        const uint32_t* Bsu = (const uint32_t*)Bs;

#pragma unroll
        for (int kk = 0; kk < KC / 8; kk++) {
            const int krow = kk * 8 + qn;
            const uint32_t* bp = Bsu + krow * BSTR + warp_n * 64 + qm;
            uint32_t bf[8][2];
#pragma unroll
            for (int nt = 0; nt < 8; nt++) {
                bf[nt][0] = bp[nt * 8];
                bf[nt][1] = bp[4 * BSTR + nt * 8];
            }
            const uint32_t* ap = Asu + krow * ASTR + warp_m * 64 + qm;
#pragma unroll
            for (int mt = 0; mt < 4; mt++) {
                uint32_t af[4];
                const uint32_t* a0 = ap + mt * 16;
                af[0] = a0[0];
                af[1] = a0[8];
                af[2] = a0[4 * ASTR];
                af[3] = a0[4 * ASTR + 8];
#pragma unroll
                for (int nt = 0; nt < 8; nt++) mma_tf32(d[mt][nt], af, bf[nt]);
            }
        }
    }
    CPA_WAIT0();

    // ---- epilogue: z = D + bias + res ; LN ; relu ; store -----------------
    const float* hin_b = hin + ((size_t)b * NN + j0) * DD;
    float* hout_b = hout + ((size_t)b * NN + j0) * DD;

#pragma unroll
    for (int mt = 0; mt < 4; mt++)
#pragma unroll
        for (int h = 0; h < 2; h++) {
            int jl = warp_m * 64 + mt * 16 + h * 8 + qm;
            const float* rrow = hin_b + (size_t)jl * DD;
            float s = 0.f, q = 0.f;
#pragma unroll
            for (int nt = 0; nt < 8; nt++) {
                int e = warp_n * 64 + nt * 8 + qn * 2;
                float2 rv = *(const float2*)(rrow + e);
                float z0 = d[mt][nt][2 * h + 0] + bias_s[e + 0] + rv.x;
                float z1 = d[mt][nt][2 * h + 1] + bias_s[e + 1] + rv.y;
                d[mt][nt][2 * h + 0] = z0;
                d[mt][nt][2 * h + 1] = z1;
                s += z0 + z1;
                q += z0 * z0 + z1 * z1;
            }
            s += __shfl_xor_sync(0xffffffffu, s, 1);
            s += __shfl_xor_sync(0xffffffffu, s, 2);
            q += __shfl_xor_sync(0xffffffffu, q, 1);
            q += __shfl_xor_sync(0xffffffffu, q, 2);
            if (qn == 0) {
                red_s[jl][warp_n][0] = s;
                red_s[jl][warp_n][1] = q;
            }
        }
    __syncthreads();

#pragma unroll
    for (int mt = 0; mt < 4; mt++)
#pragma unroll
        for (int h = 0; h < 2; h++) {
            int jl = warp_m * 64 + mt * 16 + h * 8 + qm;
            float s = red_s[jl][0][0] + red_s[jl][1][0];
            float q = red_s[jl][0][1] + red_s[jl][1][1];
            float mu = s * (1.0f / DD);
            float var = q * (1.0f / DD) - mu * mu;
            float rstd = rsqrtf(var + 1e-5f);
            float* orow = hout_b + (size_t)jl * DD;
#pragma unroll
            for (int nt = 0; nt < 8; nt++) {
                int e = warp_n * 64 + nt * 8 + qn * 2;
                float2 o;
                o.x = fmaxf(0.f, (d[mt][nt][2 * h + 0] - mu) * rstd * gamma_s[e + 0] + beta_s[e + 0]);
                o.y = fmaxf(0.f, (d[mt][nt][2 * h + 1] - mu) * rstd * gamma_s[e + 1] + beta_s[e + 1]);
                *(float2*)(orow + e) = o;
            }
        }
}

// ---------------------------------------------------------------------------
extern "C" void kernel_launch(void* const* d_in, const int* in_sizes, int n_in,
                              void* d_out, int out_size) {
    (void)in_sizes; (void)n_in; (void)out_size;
    const float* X      = (const float*)d_in[0];
    const float* adj    = (const float*)d_in[1];
    const float* Ws     = (const float*)d_in[2];
    const float* bs     = (const float*)d_in[3];
    const float* gammas = (const float*)d_in[4];
    const float* betas  = (const float*)d_in[5];
    float* out = (float*)d_out;

    float *hw, *h0, *h1;
    cudaGetSymbolAddress((void**)&hw, g_hw);
    cudaGetSymbolAddress((void**)&h0, g_h0);
    cudaGetSymbolAddress((void**)&h1, g_h1);

    static int configured = 0;
    if (!configured) {
        cudaFuncSetAttribute(gcn_kernel,
                             cudaFuncAttributeMaxDynamicSharedMemorySize,
                             DYN_SMEM);
        configured = 1;
    }

    const float* hsrc = X;
    for (int l = 0; l < 3; l++) {
        float* hdst = (l == 2) ? out : (l == 0 ? h0 : h1);
        linear_kernel<<<(BATCH * NN) / 128, 256>>>(
            hsrc, Ws + (size_t)l * DD * DD, hw);
        gcn_kernel<<<dim3(NN / CTJ, BATCH), 256, DYN_SMEM>>>(
            adj, hw, hsrc, hdst,
            bs + (size_t)l * DD, gammas + (size_t)l * DD,
            betas + (size_t)l * DD);
        hsrc = hdst;
    }
}